// round 6
// baseline (speedup 1.0000x reference)
#include <cuda_runtime.h>
#include <cuda_fp16.h>
#include <cstdint>

#define BATCH  2
#define SEQ    4096
#define DMODEL 512
#define NHEAD  8
#define DKH    64
#define MTOT   (BATCH * SEQ)
#define DD     (DMODEL * DMODEL)

// fold 1/sqrt(64) * log2(e) into Q so softmax runs in log2 domain via ex2
#define QSCALE 0.1803368801111204f

// Scratch (__device__ globals: allocation-free rule)
__device__ __half g_Xq[(size_t)MTOT * DMODEL];   // fp16 copies of inputs
__device__ __half g_Xk[(size_t)MTOT * DMODEL];
__device__ __half g_Xv[(size_t)MTOT * DMODEL];
__device__ __half g_Wh[(size_t)4 * DD];          // fp16 copies of weights
__device__ __half g_Qh[(size_t)MTOT * DMODEL];
__device__ __half g_Kh[(size_t)MTOT * DMODEL];
__device__ __half g_Vh[(size_t)MTOT * DMODEL];
__device__ __half g_AOh[(size_t)MTOT * DMODEL];

// ---------------------------------------------------------------------------
// helpers
// ---------------------------------------------------------------------------
__device__ __forceinline__ void mma16816(float* d, const uint32_t* a,
                                         uint32_t b0, uint32_t b1) {
    asm volatile(
        "mma.sync.aligned.m16n8k16.row.col.f32.f16.f16.f32 "
        "{%0,%1,%2,%3}, {%4,%5,%6,%7}, {%8,%9}, {%0,%1,%2,%3};\n"
        : "+f"(d[0]), "+f"(d[1]), "+f"(d[2]), "+f"(d[3])
        : "r"(a[0]), "r"(a[1]), "r"(a[2]), "r"(a[3]), "r"(b0), "r"(b1));
}

__device__ __forceinline__ void ldsm_x4(uint32_t& r0, uint32_t& r1,
                                        uint32_t& r2, uint32_t& r3,
                                        uint32_t addr) {
    asm volatile(
        "ldmatrix.sync.aligned.m8n8.x4.shared.b16 {%0,%1,%2,%3}, [%4];"
        : "=r"(r0), "=r"(r1), "=r"(r2), "=r"(r3) : "r"(addr));
}

__device__ __forceinline__ void ldsm_x4_trans(uint32_t& r0, uint32_t& r1,
                                              uint32_t& r2, uint32_t& r3,
                                              uint32_t addr) {
    asm volatile(
        "ldmatrix.sync.aligned.m8n8.x4.trans.shared.b16 {%0,%1,%2,%3}, [%4];"
        : "=r"(r0), "=r"(r1), "=r"(r2), "=r"(r3) : "r"(addr));
}

__device__ __forceinline__ uint32_t pack_h2(float x, float y) {
    __half2 h = __floats2half2_rn(x, y);
    return *(uint32_t*)&h;
}

__device__ __forceinline__ float ex2(float x) {
    float y;
    asm("ex2.approx.f32 %0, %1;" : "=f"(y) : "f"(x));
    return y;
}

__device__ __forceinline__ uint32_t smem_u32(const void* p) {
    return (uint32_t)__cvta_generic_to_shared(p);
}

#define CP16(dst, src) \
    asm volatile("cp.async.cg.shared.global [%0], [%1], 16;\n" \
                 :: "r"(dst), "l"(src) : "memory")
#define CP_COMMIT() asm volatile("cp.async.commit_group;\n" ::: "memory")
#define CP_WAIT(n)  asm volatile("cp.async.wait_group %0;\n" :: "n"(n) : "memory")

// ---------------------------------------------------------------------------
// fp32 -> fp16 bulk convert (vectorized)
// ---------------------------------------------------------------------------
__global__ void cvt_kernel(const float4* __restrict__ src,
                           uint2* __restrict__ dst, int n4) {
    int i = blockIdx.x * blockDim.x + threadIdx.x;
    if (i < n4) {
        float4 v = src[i];
        dst[i] = make_uint2(pack_h2(v.x, v.y), pack_h2(v.z, v.w));
    }
}

// ---------------------------------------------------------------------------
// All-fp16 projection GEMM with cp.async 2-stage pipeline.
// C[M,512] = A[M,512] @ W[512,512]^T + bias ; CTA 128x128, BK=64, 8 warps.
// ---------------------------------------------------------------------------
#define PLD 72
#define PBUF (128 * PLD)                  // halves per stage buffer
#define PROJ_SMEM_BYTES (4 * PBUF * 2)    // As[2] + Ws[2]

template <typename OutT, bool SCALE>
__global__ __launch_bounds__(256) void proj16p_kernel(
        const __half* __restrict__ A, const __half* __restrict__ W,
        const float* __restrict__ bias, OutT* __restrict__ C) {
    extern __shared__ __half ps[];

    const int tid = threadIdx.x;
    const int w = tid >> 5;
    const int l = tid & 31;
    const int g = l >> 2;
    const int t = l & 3;
    const int wm = (w >> 1) * 32;
    const int wn = (w & 1) * 64;
    const int bm = blockIdx.x * 128;
    const int bn = blockIdx.y * 128;

    const int rowA = ((l >> 3) & 1) * 8 + (l & 7);
    const int colA = ((l >> 4) & 1) * 8;
    const int rowB = ((l >> 4) & 1) * 8 + (l & 7);
    const int colB = ((l >> 3) & 1) * 8;

    const uint32_t base_u = smem_u32(ps);
    uint32_t as_u[2], ws_u[2];
    as_u[0] = base_u;
    as_u[1] = base_u + PBUF * 2;
    ws_u[0] = base_u + 2 * PBUF * 2;
    ws_u[1] = base_u + 3 * PBUF * 2;

    const int sr = tid >> 3;          // staging row 0..31 (x4 passes -> 128)
    const int sc = (tid & 7) * 8;     // staging col (halves)

    auto stageP = [&](int ks, int bf) {
        const __half* Ab = A + (size_t)bm * DMODEL + ks * 64;
        const __half* Wb = W + (size_t)bn * DMODEL + ks * 64;
        const uint32_t ad = as_u[bf], wd = ws_u[bf];
        #pragma unroll
        for (int j = 0; j < 4; j++) {
            int r = sr + 32 * j;
            CP16(ad + (r * PLD + sc) * 2, Ab + (size_t)r * DMODEL + sc);
            CP16(wd + (r * PLD + sc) * 2, Wb + (size_t)r * DMODEL + sc);
        }
        CP_COMMIT();
    };

    float acc[2][8][4];
    #pragma unroll
    for (int mt = 0; mt < 2; mt++)
        #pragma unroll
        for (int nt = 0; nt < 8; nt++)
            #pragma unroll
            for (int c = 0; c < 4; c++) acc[mt][nt][c] = 0.f;

    stageP(0, 0);

    for (int ks = 0; ks < 8; ks++) {
        if (ks + 1 < 8) { stageP(ks + 1, (ks + 1) & 1); CP_WAIT(1); }
        else           { CP_WAIT(0); }
        __syncthreads();

        const uint32_t ab = as_u[ks & 1];
        const uint32_t wb = ws_u[ks & 1];

        #pragma unroll
        for (int kk = 0; kk < 4; kk++) {
            const int ko = kk * 16;
            uint32_t a[2][4];
            #pragma unroll
            for (int mt = 0; mt < 2; mt++)
                ldsm_x4(a[mt][0], a[mt][1], a[mt][2], a[mt][3],
                        ab + ((wm + 16 * mt + rowA) * PLD + ko + colA) * 2);
            #pragma unroll
            for (int p = 0; p < 4; p++) {
                uint32_t b0, b1, b2, b3;
                ldsm_x4(b0, b1, b2, b3,
                        wb + ((wn + 16 * p + rowB) * PLD + ko + colB) * 2);
                mma16816(acc[0][2 * p],     a[0], b0, b1);
                mma16816(acc[0][2 * p + 1], a[0], b2, b3);
                mma16816(acc[1][2 * p],     a[1], b0, b1);
                mma16816(acc[1][2 * p + 1], a[1], b2, b3);
            }
        }
        __syncthreads();
    }

    #pragma unroll
    for (int mt = 0; mt < 2; mt++) {
        const int r0 = bm + wm + 16 * mt + g;
        #pragma unroll
        for (int nt = 0; nt < 8; nt++) {
            const int c = bn + wn + 8 * nt + 2 * t;
            float o0 = acc[mt][nt][0] + bias[c];
            float o1 = acc[mt][nt][1] + bias[c + 1];
            float o2 = acc[mt][nt][2] + bias[c];
            float o3 = acc[mt][nt][3] + bias[c + 1];
            if constexpr (SCALE) {
                o0 *= QSCALE; o1 *= QSCALE; o2 *= QSCALE; o3 *= QSCALE;
            }
            if constexpr (sizeof(OutT) == 4) {
                *(float2*)((float*)C + (size_t)(r0)     * DMODEL + c) = make_float2(o0, o1);
                *(float2*)((float*)C + (size_t)(r0 + 8) * DMODEL + c) = make_float2(o2, o3);
            } else {
                *(uint32_t*)((__half*)C + (size_t)(r0)     * DMODEL + c) = pack_h2(o0, o1);
                *(uint32_t*)((__half*)C + (size_t)(r0 + 8) * DMODEL + c) = pack_h2(o2, o3);
            }
        }
    }
}

// ---------------------------------------------------------------------------
// Flash attention: fp16 mma, fp32 accum, cp.async double-buffered K/V,
// V^T fragments via ldmatrix.trans (no pre-transposed V needed),
// log2-domain softmax (Q pre-scaled by QSCALE).
// ---------------------------------------------------------------------------
#define TLD 72
#define TBUF (128 * TLD)
#define QS_OFF 0
#define KS_OFF TBUF
#define VS_OFF (KS_OFF + 2 * TBUF)
#define ATTN_SMEM_BYTES ((VS_OFF + 2 * TBUF) * 2)
#define NT (SEQ / 128)

__global__ __launch_bounds__(256, 1) void attn_kernel(
        const __half* __restrict__ Qh, const __half* __restrict__ Kh,
        const __half* __restrict__ Vh, __half* __restrict__ AO) {
    extern __shared__ __half sm[];
    __half* Qs = sm + QS_OFF;

    const int tid = threadIdx.x;
    const int w = tid >> 5;
    const int l = tid & 31;
    const int g = l >> 2;
    const int t = l & 3;

    const int qt = blockIdx.x;
    const int h  = blockIdx.y;
    const int b  = blockIdx.z;

    const __half* Qg = Qh + ((size_t)b * SEQ + qt * 128) * DMODEL + h * DKH;
    const __half* Kg = Kh + (size_t)b * SEQ * DMODEL + h * DKH;
    const __half* Vg = Vh + (size_t)b * SEQ * DMODEL + h * DKH;

    const int rowA = ((l >> 3) & 1) * 8 + (l & 7);
    const int colA = ((l >> 4) & 1) * 8;
    const int rowB = ((l >> 4) & 1) * 8 + (l & 7);
    const int colB = ((l >> 3) & 1) * 8;

    const uint32_t base_u = smem_u32(sm);
    const uint32_t qs_u = base_u;
    uint32_t ks_u[2], vs_u[2];
    ks_u[0] = base_u + KS_OFF * 2;
    ks_u[1] = ks_u[0] + TBUF * 2;
    vs_u[0] = base_u + VS_OFF * 2;
    vs_u[1] = vs_u[0] + TBUF * 2;

    // Q tile (plain loads, once)
    #pragma unroll
    for (int j = 0; j < 4; j++) {
        int u = tid + 256 * j;
        int r = u >> 3, c8 = u & 7;
        *(uint4*)&Qs[r * TLD + c8 * 8] =
            *(const uint4*)(Qg + (size_t)r * DMODEL + c8 * 8);
    }

    const int sr = tid >> 3;
    const int sc = (tid & 7) * 8;

    auto stage = [&](int it, int bs) {
        const __half* Kb = Kg + (size_t)(it * 128) * DMODEL;
        const __half* Vb = Vg + (size_t)(it * 128) * DMODEL;
        const uint32_t kd = ks_u[bs], vd = vs_u[bs];
        #pragma unroll
        for (int j = 0; j < 4; j++) {
            int r = sr + 32 * j;
            CP16(kd + (r * TLD + sc) * 2, Kb + (size_t)r * DMODEL + sc);
            CP16(vd + (r * TLD + sc) * 2, Vb + (size_t)r * DMODEL + sc);
        }
        CP_COMMIT();
    };

    stage(0, 0);

    float m0 = -1e30f, m1 = -1e30f, l0 = 0.f, l1 = 0.f;
    float o[8][4];
    #pragma unroll
    for (int dt = 0; dt < 8; dt++)
        #pragma unroll
        for (int c = 0; c < 4; c++) o[dt][c] = 0.f;

    const int r0 = 16 * w + g;

    for (int it = 0; it < NT; it++) {
        if (it + 1 < NT) { stage(it + 1, (it + 1) & 1); CP_WAIT(1); }
        else             { CP_WAIT(0); }
        __syncthreads();

        const uint32_t kb = ks_u[it & 1];
        const uint32_t vb = vs_u[it & 1];

        // ---- S = Q @ K^T ----
        float s[16][4];
        #pragma unroll
        for (int nt = 0; nt < 16; nt++)
            #pragma unroll
            for (int c = 0; c < 4; c++) s[nt][c] = 0.f;

        #pragma unroll
        for (int ks = 0; ks < 4; ks++) {
            const int ko = 16 * ks;
            uint32_t a[4];
            ldsm_x4(a[0], a[1], a[2], a[3],
                    qs_u + ((16 * w + rowA) * TLD + ko + colA) * 2);
            #pragma unroll
            for (int p = 0; p < 8; p++) {
                uint32_t b0, b1, b2, b3;
                ldsm_x4(b0, b1, b2, b3,
                        kb + ((16 * p + rowB) * TLD + ko + colB) * 2);
                mma16816(s[2 * p],     a, b0, b1);
                mma16816(s[2 * p + 1], a, b2, b3);
            }
        }

        // ---- online softmax in log2 domain ----
        float mx0 = -1e30f, mx1 = -1e30f;
        #pragma unroll
        for (int nt = 0; nt < 16; nt++) {
            mx0 = fmaxf(mx0, fmaxf(s[nt][0], s[nt][1]));
            mx1 = fmaxf(mx1, fmaxf(s[nt][2], s[nt][3]));
        }
        #pragma unroll
        for (int ofs = 1; ofs <= 2; ofs <<= 1) {
            mx0 = fmaxf(mx0, __shfl_xor_sync(0xffffffffu, mx0, ofs));
            mx1 = fmaxf(mx1, __shfl_xor_sync(0xffffffffu, mx1, ofs));
        }
        const float mn0 = fmaxf(m0, mx0);
        const float mn1 = fmaxf(m1, mx1);
        float rs0 = 0.f, rs1 = 0.f;
        #pragma unroll
        for (int nt = 0; nt < 16; nt++) {
            s[nt][0] = ex2(s[nt][0] - mn0);
            s[nt][1] = ex2(s[nt][1] - mn0);
            s[nt][2] = ex2(s[nt][2] - mn1);
            s[nt][3] = ex2(s[nt][3] - mn1);
            rs0 += s[nt][0] + s[nt][1];
            rs1 += s[nt][2] + s[nt][3];
        }
        #pragma unroll
        for (int ofs = 1; ofs <= 2; ofs <<= 1) {
            rs0 += __shfl_xor_sync(0xffffffffu, rs0, ofs);
            rs1 += __shfl_xor_sync(0xffffffffu, rs1, ofs);
        }
        const float al0 = ex2(m0 - mn0);
        const float al1 = ex2(m1 - mn1);
        l0 = l0 * al0 + rs0;  m0 = mn0;
        l1 = l1 * al1 + rs1;  m1 = mn1;
        #pragma unroll
        for (int dt = 0; dt < 8; dt++) {
            o[dt][0] *= al0; o[dt][1] *= al0;
            o[dt][2] *= al1; o[dt][3] *= al1;
        }

        // ---- O += P @ V ; V^T fragments via ldmatrix.trans ----
        #pragma unroll
        for (int ks = 0; ks < 8; ks++) {
            uint32_t a[4];
            a[0] = pack_h2(s[2 * ks][0],     s[2 * ks][1]);
            a[1] = pack_h2(s[2 * ks][2],     s[2 * ks][3]);
            a[2] = pack_h2(s[2 * ks + 1][0], s[2 * ks + 1][1]);
            a[3] = pack_h2(s[2 * ks + 1][2], s[2 * ks + 1][3]);
            const int ko = 16 * ks;
            #pragma unroll
            for (int p = 0; p < 4; p++) {
                uint32_t b0, b1, b2, b3;
                // fragment (n=d, k=kv) from V[kv][d]: rows=kv(ko+rowA), cols=d
                ldsm_x4_trans(b0, b1, b2, b3,
                              vb + ((ko + rowA) * TLD + 16 * p + colA) * 2);
                mma16816(o[2 * p],     a, b0, b1);
                mma16816(o[2 * p + 1], a, b2, b3);
            }
        }
        __syncthreads();
    }

    // Epilogue: divide by l, write fp16
    __half* Og = AO + ((size_t)b * SEQ + qt * 128) * DMODEL + h * DKH;
    const float inv0 = 1.f / l0, inv1 = 1.f / l1;
    #pragma unroll
    for (int dt = 0; dt < 8; dt++) {
        const int c = 8 * dt + 2 * t;
        *(uint32_t*)(Og + (size_t)(r0)     * DMODEL + c) =
            pack_h2(o[dt][0] * inv0, o[dt][1] * inv0);
        *(uint32_t*)(Og + (size_t)(r0 + 8) * DMODEL + c) =
            pack_h2(o[dt][2] * inv1, o[dt][3] * inv1);
    }
}

// ---------------------------------------------------------------------------
extern "C" void kernel_launch(void* const* d_in, const int* in_sizes, int n_in,
                              void* d_out, int out_size) {
    const float* q   = (const float*)d_in[0];
    const float* k   = (const float*)d_in[1];
    const float* v   = (const float*)d_in[2];
    const float* w_q = (const float*)d_in[3];
    const float* b_q = (const float*)d_in[4];
    const float* w_k = (const float*)d_in[5];
    const float* b_k = (const float*)d_in[6];
    const float* w_v = (const float*)d_in[7];
    const float* b_v = (const float*)d_in[8];
    const float* w_o = (const float*)d_in[9];
    const float* b_o = (const float*)d_in[10];

    __half *Xq, *Xk, *Xv, *Wh, *Qh, *Kh, *Vh, *AOh;
    cudaGetSymbolAddress((void**)&Xq,  g_Xq);
    cudaGetSymbolAddress((void**)&Xk,  g_Xk);
    cudaGetSymbolAddress((void**)&Xv,  g_Xv);
    cudaGetSymbolAddress((void**)&Wh,  g_Wh);
    cudaGetSymbolAddress((void**)&Qh,  g_Qh);
    cudaGetSymbolAddress((void**)&Kh,  g_Kh);
    cudaGetSymbolAddress((void**)&Vh,  g_Vh);
    cudaGetSymbolAddress((void**)&AOh, g_AOh);

    cudaFuncSetAttribute(attn_kernel,
                         cudaFuncAttributeMaxDynamicSharedMemorySize,
                         ATTN_SMEM_BYTES);
    cudaFuncSetAttribute(proj16p_kernel<__half, true>,
                         cudaFuncAttributeMaxDynamicSharedMemorySize,
                         PROJ_SMEM_BYTES);
    cudaFuncSetAttribute(proj16p_kernel<__half, false>,
                         cudaFuncAttributeMaxDynamicSharedMemorySize,
                         PROJ_SMEM_BYTES);
    cudaFuncSetAttribute(proj16p_kernel<float, false>,
                         cudaFuncAttributeMaxDynamicSharedMemorySize,
                         PROJ_SMEM_BYTES);

    // fp32 -> fp16 conversions
    const int nbig4 = (MTOT * DMODEL) / 4;   // 1,048,576
    const int nw4   = DD / 4;                // 65,536
    cvt_kernel<<<nbig4 / 256, 256>>>((const float4*)q, (uint2*)Xq, nbig4);
    cvt_kernel<<<nbig4 / 256, 256>>>((const float4*)k, (uint2*)Xk, nbig4);
    cvt_kernel<<<nbig4 / 256, 256>>>((const float4*)v, (uint2*)Xv, nbig4);
    cvt_kernel<<<nw4 / 256, 256>>>((const float4*)w_q, (uint2*)(Wh + 0 * (size_t)DD), nw4);
    cvt_kernel<<<nw4 / 256, 256>>>((const float4*)w_k, (uint2*)(Wh + 1 * (size_t)DD), nw4);
    cvt_kernel<<<nw4 / 256, 256>>>((const float4*)w_v, (uint2*)(Wh + 2 * (size_t)DD), nw4);
    cvt_kernel<<<nw4 / 256, 256>>>((const float4*)w_o, (uint2*)(Wh + 3 * (size_t)DD), nw4);

    dim3 pgrid(MTOT / 128, DMODEL / 128);
    proj16p_kernel<__half, true ><<<pgrid, 256, PROJ_SMEM_BYTES>>>(Xq, Wh + 0 * (size_t)DD, b_q, Qh);
    proj16p_kernel<__half, false><<<pgrid, 256, PROJ_SMEM_BYTES>>>(Xk, Wh + 1 * (size_t)DD, b_k, Kh);
    proj16p_kernel<__half, false><<<pgrid, 256, PROJ_SMEM_BYTES>>>(Xv, Wh + 2 * (size_t)DD, b_v, Vh);

    attn_kernel<<<dim3(SEQ / 128, NHEAD, BATCH), 256, ATTN_SMEM_BYTES>>>(Qh, Kh, Vh, AOh);

    proj16p_kernel<float, false><<<pgrid, 256, PROJ_SMEM_BYTES>>>(AOh, Wh + 3 * (size_t)DD, b_o, (float*)d_out);
}